// round 13
// baseline (speedup 1.0000x reference)
#include <cuda_runtime.h>
#include <cuda_bf16.h>

// LIF over time: x[B=256, T=130, N=4096] f32 -> spikes same shape.
// Recurrence per (b,n): mem = mem*DECAY*(1-spike_prev) + x[t]; spike = mem > THRESH.
//
// R13 experiment: sm_100 256-bit global accesses (ld/st.global.cs.v8.f32).
// Each thread owns 8 consecutive floats (32B, aligned); same parallelism shape
// as the champion (131072 threads, 1024 CTAs x 128) but HALF the memory
// instructions per timestep (1 LDG.256 + 1 STG.256 vs 2+2 128-bit).

#define LIF_THRESH 0.6f
#define LIF_DECAY  0.2f

struct f8 { float v[8]; };

__device__ __forceinline__ f8 ldcs_v8(const float* p) {
    f8 r;
    asm volatile("ld.global.cs.v8.f32 {%0,%1,%2,%3,%4,%5,%6,%7}, [%8];"
                 : "=f"(r.v[0]), "=f"(r.v[1]), "=f"(r.v[2]), "=f"(r.v[3]),
                   "=f"(r.v[4]), "=f"(r.v[5]), "=f"(r.v[6]), "=f"(r.v[7])
                 : "l"(p));
    return r;
}

__device__ __forceinline__ void stcs_v8(float* p, const f8& r) {
    asm volatile("st.global.cs.v8.f32 [%0], {%1,%2,%3,%4,%5,%6,%7,%8};"
                 :: "l"(p),
                    "f"(r.v[0]), "f"(r.v[1]), "f"(r.v[2]), "f"(r.v[3]),
                    "f"(r.v[4]), "f"(r.v[5]), "f"(r.v[6]), "f"(r.v[7])
                 : "memory");
}

__global__ __launch_bounds__(128)
void lif_kernel(const float* __restrict__ x, float* __restrict__ out) {
    constexpr int T    = 130;
    constexpr int N    = 4096;
    constexpr int COLS = N / 8;        // 512 thread-columns per row

    const int idx = blockIdx.x * blockDim.x + threadIdx.x;   // 0 .. 256*512-1
    const int b   = idx >> 9;          // / 512
    const int c   = idx & (COLS - 1);  // % 512

    const size_t base = (size_t)b * (size_t)(T * N) + (size_t)c * 8;
    const float* __restrict__ xp = x   + base;
    float*       __restrict__ op = out + base;

    float m[8], f[8];
    #pragma unroll
    for (int i = 0; i < 8; ++i) { m[i] = 0.0f; f[i] = LIF_DECAY; }

    f8 cur = ldcs_v8(xp);

    #pragma unroll 2
    for (int t = 0; t < T - 1; ++t) {
        // prefetch next timestep while the update chain runs
        f8 nxt = ldcs_v8(xp + (size_t)(t + 1) * N);

        f8 sp;
        #pragma unroll
        for (int i = 0; i < 8; ++i) {
            m[i] = fmaf(m[i], f[i], cur.v[i]);
            sp.v[i] = (m[i] > LIF_THRESH) ? 1.0f : 0.0f;
            f[i]    = (m[i] > LIF_THRESH) ? 0.0f : LIF_DECAY;
        }

        stcs_v8(op + (size_t)t * N, sp);

        cur = nxt;
    }

    // tail iteration (t = T-1), no prefetch
    {
        f8 sp;
        #pragma unroll
        for (int i = 0; i < 8; ++i) {
            m[i] = fmaf(m[i], f[i], cur.v[i]);
            sp.v[i] = (m[i] > LIF_THRESH) ? 1.0f : 0.0f;
        }
        stcs_v8(op + (size_t)(T - 1) * N, sp);
    }
}

extern "C" void kernel_launch(void* const* d_in, const int* in_sizes, int n_in,
                              void* d_out, int out_size) {
    const float* x   = (const float*)d_in[0];
    float*       out = (float*)d_out;

    constexpr int B = 256, N = 4096;
    const int threads = 128;
    const int total   = B * (N / 8);          // 131072 threads (8 floats each)
    const int blocks  = total / threads;      // 1024

    lif_kernel<<<blocks, threads>>>(x, out);
}

// round 15
// speedup vs baseline: 1.0418x; 1.0418x over previous
#include <cuda_runtime.h>
#include <cuda_bf16.h>

// LIF over time: x[B=256, T=130, N=4096] f32 -> spikes same shape.
// Recurrence per (b,n): mem = mem*DECAY*(1-spike_prev) + x[t]; spike = mem > THRESH.
//
// FINAL champion — reproduced 3x at 176.2-176.5us dur_us (171.2-171.9us kernel,
// ~76% DRAM, 6.0-6.1 TB/s). Full sweep results:
//  - groups/thread {1,2,4}      -> 2 wins (occ x MLP balance)
//  - block size {64,128,256}    -> 128 wins
//  - prefetch depth {1,2}       -> 1 wins
//  - addressing {indexed, ptr}  -> indexed wins (R8)
//  - store policy {stcs, stwt}  -> stcs wins (R11)
//  - access width {128b, 256b}  -> 128b wins on harness replay timing (R13)
// Traffic at the 1.09 GB algorithmic floor; bandwidth at the part's 1:1 R/W
// stream ceiling -> ~93% of the ~160us roofline.

#define LIF_THRESH 0.6f
#define LIF_DECAY  0.2f

__global__ __launch_bounds__(128)
void lif_kernel(const float4* __restrict__ x, float4* __restrict__ out) {
    constexpr int T    = 130;
    constexpr int ROW4 = 4096 / 4;     // 1024 float4 per (b,t) row
    constexpr int HALF = ROW4 / 2;     // 512: column split per thread

    const int idx = blockIdx.x * blockDim.x + threadIdx.x;   // 0 .. 256*512-1
    const int b   = idx >> 9;          // / 512
    const int c   = idx & (HALF - 1);  // % 512

    const size_t base = (size_t)b * (size_t)(T * ROW4) + (size_t)c;
    const float4* __restrict__ xp = x   + base;
    float4*       __restrict__ op = out + base;

    // group A: column c, group B: column c+HALF
    float a0 = 0.f, a1 = 0.f, a2 = 0.f, a3 = 0.f;
    float b0 = 0.f, b1 = 0.f, b2 = 0.f, b3 = 0.f;
    float fa0 = LIF_DECAY, fa1 = LIF_DECAY, fa2 = LIF_DECAY, fa3 = LIF_DECAY;
    float fb0 = LIF_DECAY, fb1 = LIF_DECAY, fb2 = LIF_DECAY, fb3 = LIF_DECAY;

    float4 curA = __ldcs(xp);
    float4 curB = __ldcs(xp + HALF);

    #pragma unroll 2
    for (int t = 0; t < T - 1; ++t) {
        const size_t nofs = (size_t)(t + 1) * ROW4;
        // two independent prefetches in flight while the update chains run
        float4 nxtA = __ldcs(xp + nofs);
        float4 nxtB = __ldcs(xp + nofs + HALF);

        a0 = fmaf(a0, fa0, curA.x);
        a1 = fmaf(a1, fa1, curA.y);
        a2 = fmaf(a2, fa2, curA.z);
        a3 = fmaf(a3, fa3, curA.w);
        b0 = fmaf(b0, fb0, curB.x);
        b1 = fmaf(b1, fb1, curB.y);
        b2 = fmaf(b2, fb2, curB.z);
        b3 = fmaf(b3, fb3, curB.w);

        float4 spA, spB;
        spA.x = (a0 > LIF_THRESH) ? 1.0f : 0.0f;
        spA.y = (a1 > LIF_THRESH) ? 1.0f : 0.0f;
        spA.z = (a2 > LIF_THRESH) ? 1.0f : 0.0f;
        spA.w = (a3 > LIF_THRESH) ? 1.0f : 0.0f;
        spB.x = (b0 > LIF_THRESH) ? 1.0f : 0.0f;
        spB.y = (b1 > LIF_THRESH) ? 1.0f : 0.0f;
        spB.z = (b2 > LIF_THRESH) ? 1.0f : 0.0f;
        spB.w = (b3 > LIF_THRESH) ? 1.0f : 0.0f;

        fa0 = (a0 > LIF_THRESH) ? 0.0f : LIF_DECAY;
        fa1 = (a1 > LIF_THRESH) ? 0.0f : LIF_DECAY;
        fa2 = (a2 > LIF_THRESH) ? 0.0f : LIF_DECAY;
        fa3 = (a3 > LIF_THRESH) ? 0.0f : LIF_DECAY;
        fb0 = (b0 > LIF_THRESH) ? 0.0f : LIF_DECAY;
        fb1 = (b1 > LIF_THRESH) ? 0.0f : LIF_DECAY;
        fb2 = (b2 > LIF_THRESH) ? 0.0f : LIF_DECAY;
        fb3 = (b3 > LIF_THRESH) ? 0.0f : LIF_DECAY;

        const size_t ofs = (size_t)t * ROW4;
        __stcs(op + ofs,        spA);
        __stcs(op + ofs + HALF, spB);

        curA = nxtA;
        curB = nxtB;
    }

    // tail iteration (t = T-1), no prefetch
    {
        a0 = fmaf(a0, fa0, curA.x);
        a1 = fmaf(a1, fa1, curA.y);
        a2 = fmaf(a2, fa2, curA.z);
        a3 = fmaf(a3, fa3, curA.w);
        b0 = fmaf(b0, fb0, curB.x);
        b1 = fmaf(b1, fb1, curB.y);
        b2 = fmaf(b2, fb2, curB.z);
        b3 = fmaf(b3, fb3, curB.w);

        float4 spA, spB;
        spA.x = (a0 > LIF_THRESH) ? 1.0f : 0.0f;
        spA.y = (a1 > LIF_THRESH) ? 1.0f : 0.0f;
        spA.z = (a2 > LIF_THRESH) ? 1.0f : 0.0f;
        spA.w = (a3 > LIF_THRESH) ? 1.0f : 0.0f;
        spB.x = (b0 > LIF_THRESH) ? 1.0f : 0.0f;
        spB.y = (b1 > LIF_THRESH) ? 1.0f : 0.0f;
        spB.z = (b2 > LIF_THRESH) ? 1.0f : 0.0f;
        spB.w = (b3 > LIF_THRESH) ? 1.0f : 0.0f;

        const size_t ofs = (size_t)(T - 1) * ROW4;
        __stcs(op + ofs,        spA);
        __stcs(op + ofs + HALF, spB);
    }
}

extern "C" void kernel_launch(void* const* d_in, const int* in_sizes, int n_in,
                              void* d_out, int out_size) {
    const float4* x   = (const float4*)d_in[0];
    float4*       out = (float4*)d_out;

    constexpr int B = 256, N = 4096;
    const int threads = 128;
    const int total   = B * (N / 8);          // 131072 threads (2 groups each)
    const int blocks  = total / threads;      // 1024

    lif_kernel<<<blocks, threads>>>(x, out);
}

// round 16
// speedup vs baseline: 1.0450x; 1.0031x over previous
#include <cuda_runtime.h>
#include <cuda_bf16.h>

// LIF over time: x[B=256, T=130, N=4096] f32 -> spikes same shape.
// Recurrence per (b,n): mem = mem*DECAY*(1-spike_prev) + x[t]; spike = mem > THRESH.
//
// FINAL champion — reproduced 4x at 176.2-176.9us dur_us (171.2-172.6us kernel,
// ~76% DRAM, 6.0-6.1 TB/s). Full sweep results:
//  - groups/thread {1,2,4}      -> 2 wins (occ x MLP balance)
//  - block size {64,128,256}    -> 128 wins
//  - prefetch depth {1,2}       -> 1 wins
//  - addressing {indexed, ptr}  -> indexed wins (R8)
//  - store policy {stcs, stwt}  -> stcs wins (R11)
//  - access width {128b, 256b}  -> 128b wins on harness replay timing (R13)
// Traffic at the 1.09 GB algorithmic floor; bandwidth at the part's 1:1 R/W
// stream ceiling -> ~93% of the ~160us roofline.

#define LIF_THRESH 0.6f
#define LIF_DECAY  0.2f

__global__ __launch_bounds__(128)
void lif_kernel(const float4* __restrict__ x, float4* __restrict__ out) {
    constexpr int T    = 130;
    constexpr int ROW4 = 4096 / 4;     // 1024 float4 per (b,t) row
    constexpr int HALF = ROW4 / 2;     // 512: column split per thread

    const int idx = blockIdx.x * blockDim.x + threadIdx.x;   // 0 .. 256*512-1
    const int b   = idx >> 9;          // / 512
    const int c   = idx & (HALF - 1);  // % 512

    const size_t base = (size_t)b * (size_t)(T * ROW4) + (size_t)c;
    const float4* __restrict__ xp = x   + base;
    float4*       __restrict__ op = out + base;

    // group A: column c, group B: column c+HALF
    float a0 = 0.f, a1 = 0.f, a2 = 0.f, a3 = 0.f;
    float b0 = 0.f, b1 = 0.f, b2 = 0.f, b3 = 0.f;
    float fa0 = LIF_DECAY, fa1 = LIF_DECAY, fa2 = LIF_DECAY, fa3 = LIF_DECAY;
    float fb0 = LIF_DECAY, fb1 = LIF_DECAY, fb2 = LIF_DECAY, fb3 = LIF_DECAY;

    float4 curA = __ldcs(xp);
    float4 curB = __ldcs(xp + HALF);

    #pragma unroll 2
    for (int t = 0; t < T - 1; ++t) {
        const size_t nofs = (size_t)(t + 1) * ROW4;
        // two independent prefetches in flight while the update chains run
        float4 nxtA = __ldcs(xp + nofs);
        float4 nxtB = __ldcs(xp + nofs + HALF);

        a0 = fmaf(a0, fa0, curA.x);
        a1 = fmaf(a1, fa1, curA.y);
        a2 = fmaf(a2, fa2, curA.z);
        a3 = fmaf(a3, fa3, curA.w);
        b0 = fmaf(b0, fb0, curB.x);
        b1 = fmaf(b1, fb1, curB.y);
        b2 = fmaf(b2, fb2, curB.z);
        b3 = fmaf(b3, fb3, curB.w);

        float4 spA, spB;
        spA.x = (a0 > LIF_THRESH) ? 1.0f : 0.0f;
        spA.y = (a1 > LIF_THRESH) ? 1.0f : 0.0f;
        spA.z = (a2 > LIF_THRESH) ? 1.0f : 0.0f;
        spA.w = (a3 > LIF_THRESH) ? 1.0f : 0.0f;
        spB.x = (b0 > LIF_THRESH) ? 1.0f : 0.0f;
        spB.y = (b1 > LIF_THRESH) ? 1.0f : 0.0f;
        spB.z = (b2 > LIF_THRESH) ? 1.0f : 0.0f;
        spB.w = (b3 > LIF_THRESH) ? 1.0f : 0.0f;

        fa0 = (a0 > LIF_THRESH) ? 0.0f : LIF_DECAY;
        fa1 = (a1 > LIF_THRESH) ? 0.0f : LIF_DECAY;
        fa2 = (a2 > LIF_THRESH) ? 0.0f : LIF_DECAY;
        fa3 = (a3 > LIF_THRESH) ? 0.0f : LIF_DECAY;
        fb0 = (b0 > LIF_THRESH) ? 0.0f : LIF_DECAY;
        fb1 = (b1 > LIF_THRESH) ? 0.0f : LIF_DECAY;
        fb2 = (b2 > LIF_THRESH) ? 0.0f : LIF_DECAY;
        fb3 = (b3 > LIF_THRESH) ? 0.0f : LIF_DECAY;

        const size_t ofs = (size_t)t * ROW4;
        __stcs(op + ofs,        spA);
        __stcs(op + ofs + HALF, spB);

        curA = nxtA;
        curB = nxtB;
    }

    // tail iteration (t = T-1), no prefetch
    {
        a0 = fmaf(a0, fa0, curA.x);
        a1 = fmaf(a1, fa1, curA.y);
        a2 = fmaf(a2, fa2, curA.z);
        a3 = fmaf(a3, fa3, curA.w);
        b0 = fmaf(b0, fb0, curB.x);
        b1 = fmaf(b1, fb1, curB.y);
        b2 = fmaf(b2, fb2, curB.z);
        b3 = fmaf(b3, fb3, curB.w);

        float4 spA, spB;
        spA.x = (a0 > LIF_THRESH) ? 1.0f : 0.0f;
        spA.y = (a1 > LIF_THRESH) ? 1.0f : 0.0f;
        spA.z = (a2 > LIF_THRESH) ? 1.0f : 0.0f;
        spA.w = (a3 > LIF_THRESH) ? 1.0f : 0.0f;
        spB.x = (b0 > LIF_THRESH) ? 1.0f : 0.0f;
        spB.y = (b1 > LIF_THRESH) ? 1.0f : 0.0f;
        spB.z = (b2 > LIF_THRESH) ? 1.0f : 0.0f;
        spB.w = (b3 > LIF_THRESH) ? 1.0f : 0.0f;

        const size_t ofs = (size_t)(T - 1) * ROW4;
        __stcs(op + ofs,        spA);
        __stcs(op + ofs + HALF, spB);
    }
}

extern "C" void kernel_launch(void* const* d_in, const int* in_sizes, int n_in,
                              void* d_out, int out_size) {
    const float4* x   = (const float4*)d_in[0];
    float4*       out = (float4*)d_out;

    constexpr int B = 256, N = 4096;
    const int threads = 128;
    const int total   = B * (N / 8);          // 131072 threads (2 groups each)
    const int blocks  = total / threads;      // 1024

    lif_kernel<<<blocks, threads>>>(x, out);
}

// round 17
// speedup vs baseline: 1.0461x; 1.0011x over previous
#include <cuda_runtime.h>
#include <cuda_bf16.h>

// LIF over time: x[B=256, T=130, N=4096] f32 -> spikes same shape.
// Recurrence per (b,n): mem = mem*DECAY*(1-spike_prev) + x[t]; spike = mem > THRESH.
//
// FINAL champion — reproduced 5x at 176.2-176.9us dur_us (171.2-172.6us kernel,
// ~76% DRAM, 6.0-6.1 TB/s). Full sweep results:
//  - groups/thread {1,2,4}      -> 2 wins (occ x MLP balance)
//  - block size {64,128,256}    -> 128 wins
//  - prefetch depth {1,2}       -> 1 wins
//  - addressing {indexed, ptr}  -> indexed wins (R8)
//  - store policy {stcs, stwt}  -> stcs wins (R11)
//  - access width {128b, 256b}  -> 128b wins on harness replay timing (R13)
// The T-recurrence is nonlinear (threshold+reset) -> no scan reformulation;
// traffic at the 1.09 GB algorithmic floor; bandwidth at the part's 1:1 R/W
// stream ceiling -> ~93% of the ~160us roofline.

#define LIF_THRESH 0.6f
#define LIF_DECAY  0.2f

__global__ __launch_bounds__(128)
void lif_kernel(const float4* __restrict__ x, float4* __restrict__ out) {
    constexpr int T    = 130;
    constexpr int ROW4 = 4096 / 4;     // 1024 float4 per (b,t) row
    constexpr int HALF = ROW4 / 2;     // 512: column split per thread

    const int idx = blockIdx.x * blockDim.x + threadIdx.x;   // 0 .. 256*512-1
    const int b   = idx >> 9;          // / 512
    const int c   = idx & (HALF - 1);  // % 512

    const size_t base = (size_t)b * (size_t)(T * ROW4) + (size_t)c;
    const float4* __restrict__ xp = x   + base;
    float4*       __restrict__ op = out + base;

    // group A: column c, group B: column c+HALF
    float a0 = 0.f, a1 = 0.f, a2 = 0.f, a3 = 0.f;
    float b0 = 0.f, b1 = 0.f, b2 = 0.f, b3 = 0.f;
    float fa0 = LIF_DECAY, fa1 = LIF_DECAY, fa2 = LIF_DECAY, fa3 = LIF_DECAY;
    float fb0 = LIF_DECAY, fb1 = LIF_DECAY, fb2 = LIF_DECAY, fb3 = LIF_DECAY;

    float4 curA = __ldcs(xp);
    float4 curB = __ldcs(xp + HALF);

    #pragma unroll 2
    for (int t = 0; t < T - 1; ++t) {
        const size_t nofs = (size_t)(t + 1) * ROW4;
        // two independent prefetches in flight while the update chains run
        float4 nxtA = __ldcs(xp + nofs);
        float4 nxtB = __ldcs(xp + nofs + HALF);

        a0 = fmaf(a0, fa0, curA.x);
        a1 = fmaf(a1, fa1, curA.y);
        a2 = fmaf(a2, fa2, curA.z);
        a3 = fmaf(a3, fa3, curA.w);
        b0 = fmaf(b0, fb0, curB.x);
        b1 = fmaf(b1, fb1, curB.y);
        b2 = fmaf(b2, fb2, curB.z);
        b3 = fmaf(b3, fb3, curB.w);

        float4 spA, spB;
        spA.x = (a0 > LIF_THRESH) ? 1.0f : 0.0f;
        spA.y = (a1 > LIF_THRESH) ? 1.0f : 0.0f;
        spA.z = (a2 > LIF_THRESH) ? 1.0f : 0.0f;
        spA.w = (a3 > LIF_THRESH) ? 1.0f : 0.0f;
        spB.x = (b0 > LIF_THRESH) ? 1.0f : 0.0f;
        spB.y = (b1 > LIF_THRESH) ? 1.0f : 0.0f;
        spB.z = (b2 > LIF_THRESH) ? 1.0f : 0.0f;
        spB.w = (b3 > LIF_THRESH) ? 1.0f : 0.0f;

        fa0 = (a0 > LIF_THRESH) ? 0.0f : LIF_DECAY;
        fa1 = (a1 > LIF_THRESH) ? 0.0f : LIF_DECAY;
        fa2 = (a2 > LIF_THRESH) ? 0.0f : LIF_DECAY;
        fa3 = (a3 > LIF_THRESH) ? 0.0f : LIF_DECAY;
        fb0 = (b0 > LIF_THRESH) ? 0.0f : LIF_DECAY;
        fb1 = (b1 > LIF_THRESH) ? 0.0f : LIF_DECAY;
        fb2 = (b2 > LIF_THRESH) ? 0.0f : LIF_DECAY;
        fb3 = (b3 > LIF_THRESH) ? 0.0f : LIF_DECAY;

        const size_t ofs = (size_t)t * ROW4;
        __stcs(op + ofs,        spA);
        __stcs(op + ofs + HALF, spB);

        curA = nxtA;
        curB = nxtB;
    }

    // tail iteration (t = T-1), no prefetch
    {
        a0 = fmaf(a0, fa0, curA.x);
        a1 = fmaf(a1, fa1, curA.y);
        a2 = fmaf(a2, fa2, curA.z);
        a3 = fmaf(a3, fa3, curA.w);
        b0 = fmaf(b0, fb0, curB.x);
        b1 = fmaf(b1, fb1, curB.y);
        b2 = fmaf(b2, fb2, curB.z);
        b3 = fmaf(b3, fb3, curB.w);

        float4 spA, spB;
        spA.x = (a0 > LIF_THRESH) ? 1.0f : 0.0f;
        spA.y = (a1 > LIF_THRESH) ? 1.0f : 0.0f;
        spA.z = (a2 > LIF_THRESH) ? 1.0f : 0.0f;
        spA.w = (a3 > LIF_THRESH) ? 1.0f : 0.0f;
        spB.x = (b0 > LIF_THRESH) ? 1.0f : 0.0f;
        spB.y = (b1 > LIF_THRESH) ? 1.0f : 0.0f;
        spB.z = (b2 > LIF_THRESH) ? 1.0f : 0.0f;
        spB.w = (b3 > LIF_THRESH) ? 1.0f : 0.0f;

        const size_t ofs = (size_t)(T - 1) * ROW4;
        __stcs(op + ofs,        spA);
        __stcs(op + ofs + HALF, spB);
    }
}

extern "C" void kernel_launch(void* const* d_in, const int* in_sizes, int n_in,
                              void* d_out, int out_size) {
    const float4* x   = (const float4*)d_in[0];
    float4*       out = (float4*)d_out;

    constexpr int B = 256, N = 4096;
    const int threads = 128;
    const int total   = B * (N / 8);          // 131072 threads (2 groups each)
    const int blocks  = total / threads;      // 1024

    lif_kernel<<<blocks, threads>>>(x, out);
}